// round 2
// baseline (speedup 1.0000x reference)
#include <cuda_runtime.h>
#include <math.h>

// Single global accumulator for the final scalar loss.
__device__ float g_acc;

__global__ void init_k() { g_acc = 0.0f; }

// ---------------------------------------------------------------------------
// Feature matching for one (real, fake) tensor pair of shape (B, S, 512).
// Block = one s position, 512 threads, thread t owns channel d = t.
// For each batch b: L2-normalize the row real[b,s,:] and fake[b,s,:]
// (norm via block reduction), accumulate normalized values over b.
// Then mean over b, diff, square, block-sum, atomicAdd with folded scale.
// scale = weight / (4 * S * D)   (the /4 is the FEATURE_WEIGHTS mean)
// ---------------------------------------------------------------------------
__global__ void __launch_bounds__(512, 3) fm_k(const float* __restrict__ real,
                                               const float* __restrict__ fake,
                                               int B, int S, float scale)
{
    __shared__ float sm_r[16];
    __shared__ float sm_f[16];
    __shared__ float sm_inv[2];

    const int d    = threadIdx.x;
    const int lane = d & 31;
    const int w    = d >> 5;

    const long long s      = blockIdx.x;
    const long long stride = (long long)S * 512;

    const float* pr = real + s * 512 + d;
    const float* pf = fake + s * 512 + d;

    float acc_r = 0.0f, acc_f = 0.0f;

    // prefetch batch 0
    float xr = *pr;
    float xf = *pf;

    #pragma unroll 1
    for (int b = 0; b < B; ++b) {
        // prefetch next batch while we reduce this one (keeps MLP up)
        float nxr = 0.0f, nxf = 0.0f;
        if (b + 1 < B) {
            nxr = pr[(long long)(b + 1) * stride];
            nxf = pf[(long long)(b + 1) * stride];
        }

        // sum of squares across the 512 channels (two values interleaved)
        float sr = xr * xr;
        float sf = xf * xf;
        #pragma unroll
        for (int off = 16; off > 0; off >>= 1) {
            sr += __shfl_down_sync(0xffffffffu, sr, off);
            sf += __shfl_down_sync(0xffffffffu, sf, off);
        }
        if (lane == 0) { sm_r[w] = sr; sm_f[w] = sf; }
        __syncthreads();
        if (w == 0) {
            float tr = (lane < 16) ? sm_r[lane] : 0.0f;
            float tf = (lane < 16) ? sm_f[lane] : 0.0f;
            #pragma unroll
            for (int off = 8; off > 0; off >>= 1) {
                tr += __shfl_down_sync(0xffffffffu, tr, off);
                tf += __shfl_down_sync(0xffffffffu, tf, off);
            }
            if (lane == 0) {
                sm_inv[0] = 1.0f / fmaxf(sqrtf(tr), 1e-12f);
                sm_inv[1] = 1.0f / fmaxf(sqrtf(tf), 1e-12f);
            }
        }
        __syncthreads();

        acc_r += xr * sm_inv[0];
        acc_f += xf * sm_inv[1];

        xr = nxr;
        xf = nxf;
    }

    const float inv_b = 1.0f / (float)B;
    float diff = (acc_f - acc_r) * inv_b;
    float v = diff * diff;

    // block reduce v
    #pragma unroll
    for (int off = 16; off > 0; off >>= 1)
        v += __shfl_down_sync(0xffffffffu, v, off);
    if (lane == 0) sm_r[w] = v;
    __syncthreads();
    if (d == 0) {
        float t = 0.0f;
        #pragma unroll
        for (int i = 0; i < 16; ++i) t += sm_r[i];
        atomicAdd(&g_acc, t * scale);
    }
}

// ---------------------------------------------------------------------------
// Musical perceptual term over tokens (B, S) int32.
// rhythm  = mean over (B, S-1) of |ts[i+1]-ts[i]|,   ts = 256 <= t < 768
// harmony = count(interval in {6,11}) / (B*S)
// melody  = count(|pitch diff| > 12) / (B*(S-1))
// ---------------------------------------------------------------------------
__global__ void __launch_bounds__(256) mus_k(const int* __restrict__ tok, int B, int S)
{
    __shared__ float sm[8];
    const int n = B * (S - 1);
    const float c_rm = 1.0f / (float)(B * (S - 1));
    const float c_h  = 1.0f / (float)(B * S);

    float sum = 0.0f;
    for (int idx = blockIdx.x * blockDim.x + threadIdx.x; idx < n;
         idx += gridDim.x * blockDim.x) {
        int b = idx / (S - 1);
        int i = idx - b * (S - 1);
        int t0 = tok[b * S + i];
        int t1 = tok[b * S + i + 1];

        int ts0 = (t0 >= 256 && t0 < 768) ? 1 : 0;
        int ts1 = (t1 >= 256 && t1 < 768) ? 1 : 0;

        int p0 = (t0 < 128) ? t0 : 0;
        int p1 = (t1 < 128) ? t1 : 0;
        int iv = abs(p0 % 12 - p1 % 12);

        float r = (ts0 != ts1) ? 1.0f : 0.0f;
        float h = (iv == 6 || iv == 11) ? 1.0f : 0.0f;
        float m = (abs(p1 - p0) > 12) ? 1.0f : 0.0f;

        sum += r * c_rm + h * c_h + m * c_rm;
    }

    int lane = threadIdx.x & 31, w = threadIdx.x >> 5;
    #pragma unroll
    for (int off = 16; off > 0; off >>= 1)
        sum += __shfl_down_sync(0xffffffffu, sum, off);
    if (lane == 0) sm[w] = sum;
    __syncthreads();
    if (threadIdx.x == 0) {
        float t = 0.0f;
        for (int i = 0; i < (int)(blockDim.x >> 5); ++i) t += sm[i];
        atomicAdd(&g_acc, t);
    }
}

// ---------------------------------------------------------------------------
// Adversarial BCE-with-logits vs target=1: mean(softplus(-x)) * weight.
// coef = weight / n is folded in.
// ---------------------------------------------------------------------------
__global__ void __launch_bounds__(256) adv_k(const float* __restrict__ x, int n, float coef)
{
    __shared__ float sm[8];
    float sum = 0.0f;
    for (int idx = blockIdx.x * blockDim.x + threadIdx.x; idx < n;
         idx += gridDim.x * blockDim.x) {
        float v = x[idx];
        // softplus(-v) = max(-v, 0) + log1p(exp(-|v|))
        sum += fmaxf(-v, 0.0f) + log1pf(expf(-fabsf(v)));
    }
    int lane = threadIdx.x & 31, w = threadIdx.x >> 5;
    #pragma unroll
    for (int off = 16; off > 0; off >>= 1)
        sum += __shfl_down_sync(0xffffffffu, sum, off);
    if (lane == 0) sm[w] = sum;
    __syncthreads();
    if (threadIdx.x == 0) {
        float t = 0.0f;
        for (int i = 0; i < (int)(blockDim.x >> 5); ++i) t += sm[i];
        atomicAdd(&g_acc, t * coef);
    }
}

__global__ void fin_k(float* out, int n)
{
    float v = g_acc;
    for (int i = threadIdx.x; i < n; i += blockDim.x) out[i] = v;
}

extern "C" void kernel_launch(void* const* d_in, const int* in_sizes, int n_in,
                              void* d_out, int out_size)
{
    const float* real_local    = (const float*)d_in[0];
    const float* real_phrase   = (const float*)d_in[1];
    const float* real_global   = (const float*)d_in[2];
    const float* real_input    = (const float*)d_in[3];
    const float* fake_local    = (const float*)d_in[4];
    const float* fake_phrase   = (const float*)d_in[5];
    const float* fake_global   = (const float*)d_in[6];
    const float* fake_input    = (const float*)d_in[7];
    const float* local_logits  = (const float*)d_in[8];
    const float* phrase_logits = (const float*)d_in[9];
    const float* global_logits = (const float*)d_in[10];
    const int*   tokens        = (const int*)d_in[11];

    const int B = 32, S = 2048, P = 128, D = 512;

    init_k<<<1, 1>>>();

    // feature matching: scale = weight / (4 * numel(diff))
    fm_k<<<S, 512>>>(real_local,  fake_local,  B, S, 0.4f / (4.0f * S * D));
    fm_k<<<S, 512>>>(real_input,  fake_input,  B, S, 0.1f / (4.0f * S * D));
    fm_k<<<P, 512>>>(real_phrase, fake_phrase, B, P, 0.4f / (4.0f * P * D));
    fm_k<<<1, 512>>>(real_global, fake_global, B, 1, 0.2f / (4.0f * D));

    mus_k<<<128, 256>>>(tokens, B, S);

    adv_k<<<64, 256>>>(local_logits,  B * S, 0.4f / (float)(B * S));
    adv_k<<<8,  256>>>(phrase_logits, B * P, 0.4f / (float)(B * P));
    adv_k<<<1,  256>>>(global_logits, B,     0.2f / (float)B);

    fin_k<<<1, 256>>>((float*)d_out, out_size);
}

// round 7
// speedup vs baseline: 2.1311x; 2.1311x over previous
#include <cuda_runtime.h>
#include <math.h>

__device__ float g_acc;

__global__ void init_k() { g_acc = 0.0f; }

__device__ __forceinline__ float warp_sum(float v) {
    #pragma unroll
    for (int o = 16; o; o >>= 1) v += __shfl_xor_sync(0xffffffffu, v, o);
    return v;
}

// ---------------------------------------------------------------------------
// Warp-per-row feature matching, two tensor pairs fused into one grid.
// Rows [0,S) -> pair A (scaleA), rows [S,2S) -> pair B (scaleB).
// Lane owns 16 channels as 4x float4 at float4-index (lane + 32k).
// No __syncthreads anywhere in the hot loop: norm reduce is warp shuffles.
// ---------------------------------------------------------------------------
__global__ void __launch_bounds__(256, 2) fm_warp2_k(
    const float* __restrict__ rA, const float* __restrict__ fA, float scaleA,
    const float* __restrict__ rB, const float* __restrict__ fB, float scaleB,
    int B, int S)
{
    const int gwarp = blockIdx.x * 8 + (threadIdx.x >> 5);
    const int lane  = threadIdx.x & 31;

    const float* real; const float* fake; float scale; int s;
    if (gwarp < S)            { real = rA; fake = fA; scale = scaleA; s = gwarp; }
    else if (gwarp < 2 * S)   { real = rB; fake = fB; scale = scaleB; s = gwarp - S; }
    else return;

    const float4* pr = (const float4*)real + (size_t)s * 128 + lane;
    const float4* pf = (const float4*)fake + (size_t)s * 128 + lane;
    const size_t bstride = (size_t)S * 128;  // float4 stride per batch

    float ar[16], af[16];
    #pragma unroll
    for (int i = 0; i < 16; ++i) { ar[i] = 0.0f; af[i] = 0.0f; }

    #pragma unroll 2
    for (int b = 0; b < B; ++b) {
        float4 r[4], f[4];
        #pragma unroll
        for (int k = 0; k < 4; ++k) {
            r[k] = pr[(size_t)b * bstride + k * 32];
            f[k] = pf[(size_t)b * bstride + k * 32];
        }
        float sr = 0.0f, sf = 0.0f;
        #pragma unroll
        for (int k = 0; k < 4; ++k) {
            sr += r[k].x * r[k].x + r[k].y * r[k].y + r[k].z * r[k].z + r[k].w * r[k].w;
            sf += f[k].x * f[k].x + f[k].y * f[k].y + f[k].z * f[k].z + f[k].w * f[k].w;
        }
        sr = warp_sum(sr);
        sf = warp_sum(sf);
        const float ir = 1.0f / fmaxf(sqrtf(sr), 1e-12f);
        const float jf = 1.0f / fmaxf(sqrtf(sf), 1e-12f);
        #pragma unroll
        for (int k = 0; k < 4; ++k) {
            ar[4*k+0] += r[k].x * ir;  af[4*k+0] += f[k].x * jf;
            ar[4*k+1] += r[k].y * ir;  af[4*k+1] += f[k].y * jf;
            ar[4*k+2] += r[k].z * ir;  af[4*k+2] += f[k].z * jf;
            ar[4*k+3] += r[k].w * ir;  af[4*k+3] += f[k].w * jf;
        }
    }

    const float invB = 1.0f / (float)B;
    float v = 0.0f;
    #pragma unroll
    for (int i = 0; i < 16; ++i) {
        float d = (af[i] - ar[i]) * invB;
        v += d * d;
    }
    v = warp_sum(v);
    if (lane == 0) atomicAdd(&g_acc, v * scale);
}

// ---------------------------------------------------------------------------
// Batch-split feature matching for small-row-count tensors (phrase, global).
// WPR warps cooperate on one row, each handling B/WPR batches; partial
// normalized accumulators are combined in smem, then diff^2 is block-reduced.
// NW = warps per block (max 8 -> 256 threads), RPB = NW/WPR rows per block.
// ---------------------------------------------------------------------------
template<int WPR, int NW>
__global__ void __launch_bounds__(NW * 32) fm_split_k(
    const float* __restrict__ real,
    const float* __restrict__ fake,
    int B, int S, float scale)
{
    constexpr int RPB = NW / WPR;
    __shared__ float smr[RPB][512];
    __shared__ float smf[RPB][512];
    __shared__ float red[NW];

    const int wid  = threadIdx.x >> 5;
    const int lane = threadIdx.x & 31;
    const int rloc = wid / WPR;
    const int wsub = wid % WPR;
    const int s    = blockIdx.x * RPB + rloc;

    for (int i = threadIdx.x; i < RPB * 512; i += NW * 32) {
        (&smr[0][0])[i] = 0.0f;
        (&smf[0][0])[i] = 0.0f;
    }
    __syncthreads();

    if (s < S) {
        const float4* pr = (const float4*)real + (size_t)s * 128 + lane;
        const float4* pf = (const float4*)fake + (size_t)s * 128 + lane;
        const size_t bstride = (size_t)S * 128;
        const int bpw = B / WPR;
        const int b0  = wsub * bpw;

        float ar[16], af[16];
        #pragma unroll
        for (int i = 0; i < 16; ++i) { ar[i] = 0.0f; af[i] = 0.0f; }

        #pragma unroll 2
        for (int b = b0; b < b0 + bpw; ++b) {
            float4 r[4], f[4];
            #pragma unroll
            for (int k = 0; k < 4; ++k) {
                r[k] = pr[(size_t)b * bstride + k * 32];
                f[k] = pf[(size_t)b * bstride + k * 32];
            }
            float sr = 0.0f, sf = 0.0f;
            #pragma unroll
            for (int k = 0; k < 4; ++k) {
                sr += r[k].x * r[k].x + r[k].y * r[k].y + r[k].z * r[k].z + r[k].w * r[k].w;
                sf += f[k].x * f[k].x + f[k].y * f[k].y + f[k].z * f[k].z + f[k].w * f[k].w;
            }
            sr = warp_sum(sr);
            sf = warp_sum(sf);
            const float ir = 1.0f / fmaxf(sqrtf(sr), 1e-12f);
            const float jf = 1.0f / fmaxf(sqrtf(sf), 1e-12f);
            #pragma unroll
            for (int k = 0; k < 4; ++k) {
                ar[4*k+0] += r[k].x * ir;  af[4*k+0] += f[k].x * jf;
                ar[4*k+1] += r[k].y * ir;  af[4*k+1] += f[k].y * jf;
                ar[4*k+2] += r[k].z * ir;  af[4*k+2] += f[k].z * jf;
                ar[4*k+3] += r[k].w * ir;  af[4*k+3] += f[k].w * jf;
            }
        }
        #pragma unroll
        for (int k = 0; k < 4; ++k) {
            const int ch = (lane + 32 * k) * 4;
            atomicAdd(&smr[rloc][ch+0], ar[4*k+0]);
            atomicAdd(&smr[rloc][ch+1], ar[4*k+1]);
            atomicAdd(&smr[rloc][ch+2], ar[4*k+2]);
            atomicAdd(&smr[rloc][ch+3], ar[4*k+3]);
            atomicAdd(&smf[rloc][ch+0], af[4*k+0]);
            atomicAdd(&smf[rloc][ch+1], af[4*k+1]);
            atomicAdd(&smf[rloc][ch+2], af[4*k+2]);
            atomicAdd(&smf[rloc][ch+3], af[4*k+3]);
        }
    }
    __syncthreads();

    const float invB = 1.0f / (float)B;
    float v = 0.0f;
    for (int i = threadIdx.x; i < RPB * 512; i += NW * 32) {
        const int rr = i >> 9;
        const int ch = i & 511;
        if (blockIdx.x * RPB + rr < S) {
            float d = (smf[rr][ch] - smr[rr][ch]) * invB;
            v += d * d;
        }
    }
    v = warp_sum(v);
    if (lane == 0) red[wid] = v;
    __syncthreads();
    if (threadIdx.x == 0) {
        float t = 0.0f;
        #pragma unroll
        for (int i = 0; i < NW; ++i) t += red[i];
        atomicAdd(&g_acc, t * scale);
    }
}

// ---------------------------------------------------------------------------
// Musical perceptual term over tokens (B, S) int32.
// ---------------------------------------------------------------------------
__global__ void __launch_bounds__(256) mus_k(const int* __restrict__ tok, int B, int S)
{
    __shared__ float sm[8];
    const int n = B * (S - 1);
    const float c_rm = 1.0f / (float)(B * (S - 1));
    const float c_h  = 1.0f / (float)(B * S);

    float sum = 0.0f;
    for (int idx = blockIdx.x * blockDim.x + threadIdx.x; idx < n;
         idx += gridDim.x * blockDim.x) {
        int b = idx / (S - 1);
        int i = idx - b * (S - 1);
        int t0 = tok[b * S + i];
        int t1 = tok[b * S + i + 1];

        int ts0 = (t0 >= 256 && t0 < 768) ? 1 : 0;
        int ts1 = (t1 >= 256 && t1 < 768) ? 1 : 0;

        int p0 = (t0 < 128) ? t0 : 0;
        int p1 = (t1 < 128) ? t1 : 0;
        int iv = abs(p0 % 12 - p1 % 12);

        float r = (ts0 != ts1) ? 1.0f : 0.0f;
        float h = (iv == 6 || iv == 11) ? 1.0f : 0.0f;
        float m = (abs(p1 - p0) > 12) ? 1.0f : 0.0f;

        sum += r * c_rm + h * c_h + m * c_rm;
    }

    int lane = threadIdx.x & 31, w = threadIdx.x >> 5;
    sum = warp_sum(sum);
    if (lane == 0) sm[w] = sum;
    __syncthreads();
    if (threadIdx.x == 0) {
        float t = 0.0f;
        #pragma unroll
        for (int i = 0; i < 8; ++i) t += sm[i];
        atomicAdd(&g_acc, t);
    }
}

// ---------------------------------------------------------------------------
// Three adversarial BCE terms fused: sum_i coef_i * sum(softplus(-x_i)).
// ---------------------------------------------------------------------------
__global__ void __launch_bounds__(256) adv3_k(
    const float* __restrict__ x0, int n0, float c0,
    const float* __restrict__ x1, int n1, float c1,
    const float* __restrict__ x2, int n2, float c2)
{
    __shared__ float sm[8];
    const int n = n0 + n1 + n2;
    float sum = 0.0f;
    for (int idx = blockIdx.x * blockDim.x + threadIdx.x; idx < n;
         idx += gridDim.x * blockDim.x) {
        float v, c;
        if (idx < n0)           { v = x0[idx];            c = c0; }
        else if (idx < n0 + n1) { v = x1[idx - n0];       c = c1; }
        else                    { v = x2[idx - n0 - n1];  c = c2; }
        sum += c * (fmaxf(-v, 0.0f) + log1pf(expf(-fabsf(v))));
    }
    int lane = threadIdx.x & 31, w = threadIdx.x >> 5;
    sum = warp_sum(sum);
    if (lane == 0) sm[w] = sum;
    __syncthreads();
    if (threadIdx.x == 0) {
        float t = 0.0f;
        #pragma unroll
        for (int i = 0; i < 8; ++i) t += sm[i];
        atomicAdd(&g_acc, t);
    }
}

__global__ void fin_k(float* out, int n)
{
    float v = g_acc;
    for (int i = threadIdx.x; i < n; i += blockDim.x) out[i] = v;
}

extern "C" void kernel_launch(void* const* d_in, const int* in_sizes, int n_in,
                              void* d_out, int out_size)
{
    const float* real_local    = (const float*)d_in[0];
    const float* real_phrase   = (const float*)d_in[1];
    const float* real_global   = (const float*)d_in[2];
    const float* real_input    = (const float*)d_in[3];
    const float* fake_local    = (const float*)d_in[4];
    const float* fake_phrase   = (const float*)d_in[5];
    const float* fake_global   = (const float*)d_in[6];
    const float* fake_input    = (const float*)d_in[7];
    const float* local_logits  = (const float*)d_in[8];
    const float* phrase_logits = (const float*)d_in[9];
    const float* global_logits = (const float*)d_in[10];
    const int*   tokens        = (const int*)d_in[11];

    const int B = 32, S = 2048, P = 128, D = 512;

    init_k<<<1, 1>>>();

    // local + input fused: 2S rows, 8 warps/block -> 2S/8 blocks
    fm_warp2_k<<<(2 * S) / 8, 256>>>(
        real_local, fake_local, 0.4f / (4.0f * S * D),
        real_input, fake_input, 0.1f / (4.0f * S * D),
        B, S);

    // phrase: 4 warps/row, 8 warps/block -> 2 rows/block
    fm_split_k<4, 8><<<P / 2, 256>>>(real_phrase, fake_phrase, B, P,
                                     0.4f / (4.0f * P * D));

    // global: 1 row, 8 warps on it (4 batches per warp), 256 threads
    fm_split_k<8, 8><<<1, 256>>>(real_global, fake_global, B, 1,
                                 0.2f / (4.0f * D));

    mus_k<<<64, 256>>>(tokens, B, S);

    adv3_k<<<48, 256>>>(local_logits,  B * S, 0.4f / (float)(B * S),
                        phrase_logits, B * P, 0.4f / (float)(B * P),
                        global_logits, B,     0.2f / (float)B);

    fin_k<<<1, 256>>>((float*)d_out, out_size);
}

// round 9
// speedup vs baseline: 2.6901x; 1.2623x over previous
#include <cuda_runtime.h>
#include <math.h>

// Per-block partial results. Every block of mega_k writes exactly one slot,
// so no zero-init kernel is needed and results are deterministic.
#define N_GLOBAL_BLK  1
#define N_PHRASE_BLK  64
#define N_MUS_BLK     32
#define N_ADV_BLK     16
#define N_SMALL_BLK   (N_GLOBAL_BLK + N_PHRASE_BLK + N_MUS_BLK + N_ADV_BLK)   // 113
#define N_STREAM_BLK  512
#define N_BLOCKS      (N_SMALL_BLK + N_STREAM_BLK)                            // 625

// Shared scratch: worst case is fm_split_body<4,8> (RPB=2):
// smr[2*512] + smf[2*512] + red[8] -> 2056 floats. Pad to 2064.
#define SM_FLOATS (2 * 2 * 512 + 16)

__device__ float g_part[N_BLOCKS];

__device__ __forceinline__ float warp_sum(float v) {
    #pragma unroll
    for (int o = 16; o; o >>= 1) v += __shfl_xor_sync(0xffffffffu, v, o);
    return v;
}

// ---------------------------------------------------------------------------
// Streaming feature-matching body: warp owns one full 512-ch row.
// Returns this warp's v*scale contribution (valid on all lanes after warp_sum).
// ---------------------------------------------------------------------------
__device__ __forceinline__ float fm_row_warp(
    const float* __restrict__ real, const float* __restrict__ fake,
    int s, int B, int S, float scale, int lane)
{
    const float4* pr = (const float4*)real + (size_t)s * 128 + lane;
    const float4* pf = (const float4*)fake + (size_t)s * 128 + lane;
    const size_t bstride = (size_t)S * 128;

    float ar[16], af[16];
    #pragma unroll
    for (int i = 0; i < 16; ++i) { ar[i] = 0.0f; af[i] = 0.0f; }

    #pragma unroll 2
    for (int b = 0; b < B; ++b) {
        float4 r[4], f[4];
        #pragma unroll
        for (int k = 0; k < 4; ++k) {
            r[k] = pr[(size_t)b * bstride + k * 32];
            f[k] = pf[(size_t)b * bstride + k * 32];
        }
        float sr = 0.0f, sf = 0.0f;
        #pragma unroll
        for (int k = 0; k < 4; ++k) {
            sr += r[k].x * r[k].x + r[k].y * r[k].y + r[k].z * r[k].z + r[k].w * r[k].w;
            sf += f[k].x * f[k].x + f[k].y * f[k].y + f[k].z * f[k].z + f[k].w * f[k].w;
        }
        sr = warp_sum(sr);
        sf = warp_sum(sf);
        const float ir = 1.0f / fmaxf(sqrtf(sr), 1e-12f);
        const float jf = 1.0f / fmaxf(sqrtf(sf), 1e-12f);
        #pragma unroll
        for (int k = 0; k < 4; ++k) {
            ar[4*k+0] += r[k].x * ir;  af[4*k+0] += f[k].x * jf;
            ar[4*k+1] += r[k].y * ir;  af[4*k+1] += f[k].y * jf;
            ar[4*k+2] += r[k].z * ir;  af[4*k+2] += f[k].z * jf;
            ar[4*k+3] += r[k].w * ir;  af[4*k+3] += f[k].w * jf;
        }
    }

    const float invB = 1.0f / (float)B;
    float v = 0.0f;
    #pragma unroll
    for (int i = 0; i < 16; ++i) {
        float d = (af[i] - ar[i]) * invB;
        v += d * d;
    }
    return warp_sum(v) * scale;
}

// ---------------------------------------------------------------------------
// Batch-split body for small-row tensors: WPR warps per row, partial
// normalized accumulators combined in smem. Writes block partial to g_part.
// sm must have at least 2*RPB*512 + NW floats.
// ---------------------------------------------------------------------------
template<int WPR, int NW>
__device__ __forceinline__ void fm_split_body(
    float* sm,
    const float* __restrict__ real, const float* __restrict__ fake,
    int B, int S, float scale, int row_blk)
{
    constexpr int RPB = NW / WPR;
    float* smr = sm;                     // [RPB][512]
    float* smf = sm + RPB * 512;         // [RPB][512]
    float* red = sm + 2 * RPB * 512;     // [NW]

    const int wid  = threadIdx.x >> 5;
    const int lane = threadIdx.x & 31;
    const int rloc = wid / WPR;
    const int wsub = wid % WPR;
    const int s    = row_blk * RPB + rloc;

    for (int i = threadIdx.x; i < RPB * 512; i += NW * 32) {
        smr[i] = 0.0f;
        smf[i] = 0.0f;
    }
    __syncthreads();

    if (s < S) {
        const float4* pr = (const float4*)real + (size_t)s * 128 + lane;
        const float4* pf = (const float4*)fake + (size_t)s * 128 + lane;
        const size_t bstride = (size_t)S * 128;
        const int bpw = B / WPR;
        const int b0  = wsub * bpw;

        float ar[16], af[16];
        #pragma unroll
        for (int i = 0; i < 16; ++i) { ar[i] = 0.0f; af[i] = 0.0f; }

        #pragma unroll 2
        for (int b = b0; b < b0 + bpw; ++b) {
            float4 r[4], f[4];
            #pragma unroll
            for (int k = 0; k < 4; ++k) {
                r[k] = pr[(size_t)b * bstride + k * 32];
                f[k] = pf[(size_t)b * bstride + k * 32];
            }
            float sr = 0.0f, sf = 0.0f;
            #pragma unroll
            for (int k = 0; k < 4; ++k) {
                sr += r[k].x * r[k].x + r[k].y * r[k].y + r[k].z * r[k].z + r[k].w * r[k].w;
                sf += f[k].x * f[k].x + f[k].y * f[k].y + f[k].z * f[k].z + f[k].w * f[k].w;
            }
            sr = warp_sum(sr);
            sf = warp_sum(sf);
            const float ir = 1.0f / fmaxf(sqrtf(sr), 1e-12f);
            const float jf = 1.0f / fmaxf(sqrtf(sf), 1e-12f);
            #pragma unroll
            for (int k = 0; k < 4; ++k) {
                ar[4*k+0] += r[k].x * ir;  af[4*k+0] += f[k].x * jf;
                ar[4*k+1] += r[k].y * ir;  af[4*k+1] += f[k].y * jf;
                ar[4*k+2] += r[k].z * ir;  af[4*k+2] += f[k].z * jf;
                ar[4*k+3] += r[k].w * ir;  af[4*k+3] += f[k].w * jf;
            }
        }
        #pragma unroll
        for (int k = 0; k < 4; ++k) {
            const int ch = rloc * 512 + (lane + 32 * k) * 4;
            atomicAdd(&smr[ch+0], ar[4*k+0]);
            atomicAdd(&smr[ch+1], ar[4*k+1]);
            atomicAdd(&smr[ch+2], ar[4*k+2]);
            atomicAdd(&smr[ch+3], ar[4*k+3]);
            atomicAdd(&smf[ch+0], af[4*k+0]);
            atomicAdd(&smf[ch+1], af[4*k+1]);
            atomicAdd(&smf[ch+2], af[4*k+2]);
            atomicAdd(&smf[ch+3], af[4*k+3]);
        }
    }
    __syncthreads();

    const float invB = 1.0f / (float)B;
    float v = 0.0f;
    for (int i = threadIdx.x; i < RPB * 512; i += NW * 32) {
        const int rr = i >> 9;
        if (row_blk * RPB + rr < S) {
            float d = (smf[i] - smr[i]) * invB;
            v += d * d;
        }
    }
    v = warp_sum(v);
    if (lane == 0) red[wid] = v;
    __syncthreads();
    if (threadIdx.x == 0) {
        float t = 0.0f;
        #pragma unroll
        for (int i = 0; i < NW; ++i) t += red[i];
        g_part[blockIdx.x] = t * scale;
    }
}

// ---------------------------------------------------------------------------
// The mega kernel: block-range dispatch. Small-work blocks come first so they
// schedule in wave 1 and hide under the 512 streaming blocks.
//   [0, 1)      : global feature
//   [1, 65)     : phrase feature (2 rows/block)
//   [65, 97)    : musical perceptual (tokens)
//   [97, 113)   : adversarial BCE x3
//   [113, 625)  : local+input streaming (8 rows/blk)
// ---------------------------------------------------------------------------
__global__ void __launch_bounds__(256, 2) mega_k(
    const float* __restrict__ real_local,  const float* __restrict__ fake_local,
    const float* __restrict__ real_phrase, const float* __restrict__ fake_phrase,
    const float* __restrict__ real_global, const float* __restrict__ fake_global,
    const float* __restrict__ real_input,  const float* __restrict__ fake_input,
    const float* __restrict__ local_logits, const float* __restrict__ phrase_logits,
    const float* __restrict__ global_logits, const int* __restrict__ tokens,
    int B, int S, int P)
{
    __shared__ float sm_big[SM_FLOATS];

    const int blk  = blockIdx.x;
    const int lane = threadIdx.x & 31;
    const int wid  = threadIdx.x >> 5;
    const int D = 512;

    if (blk < N_GLOBAL_BLK) {
        // global feature: 1 row, 8 warps (4 batches each)
        fm_split_body<8, 8>(sm_big, real_global, fake_global, B, 1,
                            0.2f / (4.0f * D), 0);
        return;
    }

    if (blk < N_GLOBAL_BLK + N_PHRASE_BLK) {
        // phrase: 4 warps/row, 2 rows/block
        fm_split_body<4, 8>(sm_big, real_phrase, fake_phrase, B, P,
                            0.4f / (4.0f * P * D), blk - N_GLOBAL_BLK);
        return;
    }

    if (blk < N_GLOBAL_BLK + N_PHRASE_BLK + N_MUS_BLK) {
        // musical perceptual over tokens
        const int mblk = blk - N_GLOBAL_BLK - N_PHRASE_BLK;
        const int n = B * (S - 1);
        const float c_rm = 1.0f / (float)(B * (S - 1));
        const float c_h  = 1.0f / (float)(B * S);
        float sum = 0.0f;
        for (int idx = mblk * 256 + threadIdx.x; idx < n; idx += N_MUS_BLK * 256) {
            int b = idx / (S - 1);
            int i = idx - b * (S - 1);
            int t0 = tokens[b * S + i];
            int t1 = tokens[b * S + i + 1];
            int ts0 = (t0 >= 256 && t0 < 768) ? 1 : 0;
            int ts1 = (t1 >= 256 && t1 < 768) ? 1 : 0;
            int p0 = (t0 < 128) ? t0 : 0;
            int p1 = (t1 < 128) ? t1 : 0;
            int iv = abs(p0 % 12 - p1 % 12);
            float r = (ts0 != ts1) ? 1.0f : 0.0f;
            float h = (iv == 6 || iv == 11) ? 1.0f : 0.0f;
            float m = (abs(p1 - p0) > 12) ? 1.0f : 0.0f;
            sum += r * c_rm + h * c_h + m * c_rm;
        }
        sum = warp_sum(sum);
        if (lane == 0) sm_big[wid] = sum;
        __syncthreads();
        if (threadIdx.x == 0) {
            float t = 0.0f;
            #pragma unroll
            for (int i = 0; i < 8; ++i) t += sm_big[i];
            g_part[blockIdx.x] = t;
        }
        return;
    }

    if (blk < N_SMALL_BLK) {
        // adversarial: three BCE terms over concatenated index space
        const int ablk = blk - N_GLOBAL_BLK - N_PHRASE_BLK - N_MUS_BLK;
        const int n0 = B * S, n1 = B * P, n2 = B;
        const float c0 = 0.4f / (float)n0;
        const float c1 = 0.4f / (float)n1;
        const float c2 = 0.2f / (float)n2;
        const int n = n0 + n1 + n2;
        float sum = 0.0f;
        for (int idx = ablk * 256 + threadIdx.x; idx < n; idx += N_ADV_BLK * 256) {
            float v, c;
            if (idx < n0)           { v = local_logits[idx];             c = c0; }
            else if (idx < n0 + n1) { v = phrase_logits[idx - n0];       c = c1; }
            else                    { v = global_logits[idx - n0 - n1];  c = c2; }
            sum += c * (fmaxf(-v, 0.0f) + log1pf(expf(-fabsf(v))));
        }
        sum = warp_sum(sum);
        if (lane == 0) sm_big[wid] = sum;
        __syncthreads();
        if (threadIdx.x == 0) {
            float t = 0.0f;
            #pragma unroll
            for (int i = 0; i < 8; ++i) t += sm_big[i];
            g_part[blockIdx.x] = t;
        }
        return;
    }

    // streaming local + input: gwarp in [0, 2S)
    const int gwarp = (blk - N_SMALL_BLK) * 8 + wid;
    float v;
    if (gwarp < S) {
        v = fm_row_warp(real_local, fake_local, gwarp, B, S,
                        0.4f / (4.0f * S * D), lane);
    } else {
        v = fm_row_warp(real_input, fake_input, gwarp - S, B, S,
                        0.1f / (4.0f * S * D), lane);
    }
    if (lane == 0) sm_big[wid] = v;
    __syncthreads();
    if (threadIdx.x == 0) {
        float t = 0.0f;
        #pragma unroll
        for (int i = 0; i < 8; ++i) t += sm_big[i];
        g_part[blockIdx.x] = t;
    }
}

// ---------------------------------------------------------------------------
// Finalize: sum all block partials, broadcast to d_out.
// ---------------------------------------------------------------------------
__global__ void __launch_bounds__(256) fin_k(float* out, int n)
{
    __shared__ float sm[8];
    float sum = 0.0f;
    for (int i = threadIdx.x; i < N_BLOCKS; i += 256) sum += g_part[i];
    sum = warp_sum(sum);
    const int lane = threadIdx.x & 31, w = threadIdx.x >> 5;
    if (lane == 0) sm[w] = sum;
    __syncthreads();
    if (threadIdx.x == 0) {
        float t = 0.0f;
        #pragma unroll
        for (int i = 0; i < 8; ++i) t += sm[i];
        sm[0] = t;
    }
    __syncthreads();
    const float v = sm[0];
    for (int i = threadIdx.x; i < n; i += 256) out[i] = v;
}

extern "C" void kernel_launch(void* const* d_in, const int* in_sizes, int n_in,
                              void* d_out, int out_size)
{
    const float* real_local    = (const float*)d_in[0];
    const float* real_phrase   = (const float*)d_in[1];
    const float* real_global   = (const float*)d_in[2];
    const float* real_input    = (const float*)d_in[3];
    const float* fake_local    = (const float*)d_in[4];
    const float* fake_phrase   = (const float*)d_in[5];
    const float* fake_global   = (const float*)d_in[6];
    const float* fake_input    = (const float*)d_in[7];
    const float* local_logits  = (const float*)d_in[8];
    const float* phrase_logits = (const float*)d_in[9];
    const float* global_logits = (const float*)d_in[10];
    const int*   tokens        = (const int*)d_in[11];

    const int B = 32, S = 2048, P = 128;

    mega_k<<<N_BLOCKS, 256>>>(
        real_local, fake_local,
        real_phrase, fake_phrase,
        real_global, fake_global,
        real_input, fake_input,
        local_logits, phrase_logits, global_logits, tokens,
        B, S, P);

    fin_k<<<1, 256>>>((float*)d_out, out_size);
}